// round 2
// baseline (speedup 1.0000x reference)
#include <cuda_runtime.h>
#include <math_constants.h>

// Problem constants
#define BATCH 4
#define SEQ   2048
#define CH    1024
#define MROWS (BATCH * SEQ)   // 8192
static __device__ float g_Q[(size_t)MROWS * CH];
static __device__ float g_K[(size_t)MROWS * CH];
static __device__ float g_V[(size_t)MROWS * CH];
static __device__ float g_S[(size_t)BATCH * SEQ * SEQ];

// ---------------------------------------------------------------------------
// Kernel 1: fused QKV projection.  y = x @ W^T for W in {Wq,Wk,Wv}.
// x: [MROWS, CH] row-major (K-major), W: [CH, CH] row-major (K-major).
// Tiling: BM=BN=64, BK=16, 256 threads, 4x4 microtile. A-tile shared by 3 outputs.
// ---------------------------------------------------------------------------
__global__ __launch_bounds__(256) void qkv_kernel(
    const float* __restrict__ x,
    const float* __restrict__ Wq,
    const float* __restrict__ Wk,
    const float* __restrict__ Wv)
{
    __shared__ float As[16][64];
    __shared__ float Qs[16][64];
    __shared__ float Ks[16][64];
    __shared__ float Vs[16][64];

    const int m0 = blockIdx.y * 64;
    const int n0 = blockIdx.x * 64;
    const int tid = threadIdx.x;
    const int lr = tid >> 2;          // 0..63 tile row for loads
    const int lc = (tid & 3) * 4;     // 0,4,8,12 col-quad for loads
    const int tx = tid & 15;          // 0..15
    const int ty = tid >> 4;          // 0..15

    float aq[4][4] = {}, ak[4][4] = {}, av[4][4] = {};

    for (int k0 = 0; k0 < CH; k0 += 16) {
        float4 a = *(const float4*)(x  + (size_t)(m0 + lr) * CH + k0 + lc);
        float4 q = *(const float4*)(Wq + (size_t)(n0 + lr) * CH + k0 + lc);
        float4 k = *(const float4*)(Wk + (size_t)(n0 + lr) * CH + k0 + lc);
        float4 v = *(const float4*)(Wv + (size_t)(n0 + lr) * CH + k0 + lc);
        As[lc+0][lr] = a.x; As[lc+1][lr] = a.y; As[lc+2][lr] = a.z; As[lc+3][lr] = a.w;
        Qs[lc+0][lr] = q.x; Qs[lc+1][lr] = q.y; Qs[lc+2][lr] = q.z; Qs[lc+3][lr] = q.w;
        Ks[lc+0][lr] = k.x; Ks[lc+1][lr] = k.y; Ks[lc+2][lr] = k.z; Ks[lc+3][lr] = k.w;
        Vs[lc+0][lr] = v.x; Vs[lc+1][lr] = v.y; Vs[lc+2][lr] = v.z; Vs[lc+3][lr] = v.w;
        __syncthreads();

        #pragma unroll
        for (int kk = 0; kk < 16; kk++) {
            float4 af = *(const float4*)&As[kk][ty * 4];
            float4 qf = *(const float4*)&Qs[kk][tx * 4];
            float4 kf = *(const float4*)&Ks[kk][tx * 4];
            float4 vf = *(const float4*)&Vs[kk][tx * 4];
            const float afv[4] = {af.x, af.y, af.z, af.w};
            const float qfv[4] = {qf.x, qf.y, qf.z, qf.w};
            const float kfv[4] = {kf.x, kf.y, kf.z, kf.w};
            const float vfv[4] = {vf.x, vf.y, vf.z, vf.w};
            #pragma unroll
            for (int i = 0; i < 4; i++) {
                #pragma unroll
                for (int j = 0; j < 4; j++) {
                    aq[i][j] = fmaf(afv[i], qfv[j], aq[i][j]);
                    ak[i][j] = fmaf(afv[i], kfv[j], ak[i][j]);
                    av[i][j] = fmaf(afv[i], vfv[j], av[i][j]);
                }
            }
        }
        __syncthreads();
    }

    #pragma unroll
    for (int i = 0; i < 4; i++) {
        size_t off = (size_t)(m0 + ty * 4 + i) * CH + n0 + tx * 4;
        *(float4*)(g_Q + off) = make_float4(aq[i][0], aq[i][1], aq[i][2], aq[i][3]);
        *(float4*)(g_K + off) = make_float4(ak[i][0], ak[i][1], ak[i][2], ak[i][3]);
        *(float4*)(g_V + off) = make_float4(av[i][0], av[i][1], av[i][2], av[i][3]);
    }
}

// ---------------------------------------------------------------------------
// Kernel 2: S = scale * Q @ K^T with causal mask. Skips tiles strictly above
// the diagonal (fills -inf). Per batch.
// ---------------------------------------------------------------------------
__global__ __launch_bounds__(256) void scores_kernel()
{
    const int b  = blockIdx.z;
    const int t0 = blockIdx.y * 64;   // query rows
    const int s0 = blockIdx.x * 64;   // key cols
    const int tid = threadIdx.x;
    float* Sb = g_S + (size_t)b * SEQ * SEQ;

    if (s0 > t0 + 63) {
        // tile entirely masked
        const float4 ninf = make_float4(-CUDART_INF_F, -CUDART_INF_F,
                                        -CUDART_INF_F, -CUDART_INF_F);
        int r  = tid >> 2;             // 0..63
        int c0 = (tid & 3) * 16;       // 16 floats per thread
        float* p = Sb + (size_t)(t0 + r) * SEQ + s0 + c0;
        *(float4*)(p + 0)  = ninf;
        *(float4*)(p + 4)  = ninf;
        *(float4*)(p + 8)  = ninf;
        *(float4*)(p + 12) = ninf;
        return;
    }

    __shared__ float Aq[16][64];
    __shared__ float Bk[16][64];
    const float* Q = g_Q + (size_t)b * SEQ * CH;
    const float* K = g_K + (size_t)b * SEQ * CH;

    const int lr = tid >> 2;
    const int lc = (tid & 3) * 4;
    const int tx = tid & 15;
    const int ty = tid >> 4;

    float acc[4][4] = {};

    for (int k0 = 0; k0 < CH; k0 += 16) {
        float4 a = *(const float4*)(Q + (size_t)(t0 + lr) * CH + k0 + lc);
        float4 c = *(const float4*)(K + (size_t)(s0 + lr) * CH + k0 + lc);
        Aq[lc+0][lr] = a.x; Aq[lc+1][lr] = a.y; Aq[lc+2][lr] = a.z; Aq[lc+3][lr] = a.w;
        Bk[lc+0][lr] = c.x; Bk[lc+1][lr] = c.y; Bk[lc+2][lr] = c.z; Bk[lc+3][lr] = c.w;
        __syncthreads();
        #pragma unroll
        for (int kk = 0; kk < 16; kk++) {
            float4 af = *(const float4*)&Aq[kk][ty * 4];
            float4 bf = *(const float4*)&Bk[kk][tx * 4];
            const float afv[4] = {af.x, af.y, af.z, af.w};
            const float bfv[4] = {bf.x, bf.y, bf.z, bf.w};
            #pragma unroll
            for (int i = 0; i < 4; i++)
                #pragma unroll
                for (int j = 0; j < 4; j++)
                    acc[i][j] = fmaf(afv[i], bfv[j], acc[i][j]);
        }
        __syncthreads();
    }

    const float scale = 0.03125f;  // 1/sqrt(1024)
    #pragma unroll
    for (int i = 0; i < 4; i++) {
        int t = t0 + ty * 4 + i;
        float out[4];
        #pragma unroll
        for (int j = 0; j < 4; j++) {
            int s = s0 + tx * 4 + j;
            out[j] = (s <= t) ? acc[i][j] * scale : -CUDART_INF_F;
        }
        *(float4*)(Sb + (size_t)t * SEQ + s0 + tx * 4) =
            make_float4(out[0], out[1], out[2], out[3]);
    }
}

// ---------------------------------------------------------------------------
// Kernel 3: row softmax over S (masked entries are -inf -> become 0).
// One block (256 thr) per row of length SEQ=2048.
// ---------------------------------------------------------------------------
__global__ __launch_bounds__(256) void softmax_kernel()
{
    const int t = blockIdx.x;
    const int b = blockIdx.y;
    float* row = g_S + ((size_t)b * SEQ + t) * SEQ;
    const int tid = threadIdx.x;

    float v[8];
    float m = -CUDART_INF_F;
    #pragma unroll
    for (int i = 0; i < 8; i++) {
        v[i] = row[tid + i * 256];
        m = fmaxf(m, v[i]);
    }
    #pragma unroll
    for (int o = 16; o; o >>= 1) m = fmaxf(m, __shfl_xor_sync(~0u, m, o));

    __shared__ float smax[8];
    __shared__ float ssum[8];
    if ((tid & 31) == 0) smax[tid >> 5] = m;
    __syncthreads();
    m = smax[0];
    #pragma unroll
    for (int i = 1; i < 8; i++) m = fmaxf(m, smax[i]);

    float s = 0.f;
    #pragma unroll
    for (int i = 0; i < 8; i++) {
        v[i] = expf(v[i] - m);   // exp(-inf - m) = 0 for masked entries
        s += v[i];
    }
    #pragma unroll
    for (int o = 16; o; o >>= 1) s += __shfl_xor_sync(~0u, s, o);
    if ((tid & 31) == 0) ssum[tid >> 5] = s;
    __syncthreads();
    s = 0.f;
    #pragma unroll
    for (int i = 0; i < 8; i++) s += ssum[i];

    const float inv = 1.0f / s;
    #pragma unroll
    for (int i = 0; i < 8; i++) row[tid + i * 256] = v[i] * inv;
}

// ---------------------------------------------------------------------------
// Kernel 4: O = P @ V.  P: [SEQ, SEQ] row-major (K-major),
// V: [SEQ, CH] row-major ([k][n], no transpose needed).
// K-loop clipped at causal boundary (P is exactly 0 beyond t0+63).
// ---------------------------------------------------------------------------
__global__ __launch_bounds__(256) void av_kernel(float* __restrict__ out)
{
    const int b  = blockIdx.z;
    const int t0 = blockIdx.y * 64;
    const int n0 = blockIdx.x * 64;
    const int tid = threadIdx.x;

    const float* P = g_S + (size_t)b * SEQ * SEQ;
    const float* V = g_V + (size_t)b * SEQ * CH;

    __shared__ float Ps[16][64];
    __shared__ float Vs[16][64];

    const int lr = tid >> 2;          // P-tile row 0..63
    const int lc = (tid & 3) * 4;     // P-tile col quad
    const int vr = tid >> 4;          // V-tile row 0..15
    const int vc = (tid & 15) * 4;    // V-tile col quad
    const int tx = tid & 15;
    const int ty = tid >> 4;

    float acc[4][4] = {};

    const int kmax = t0 + 64;         // multiple of 16; P == 0 for s > t0+63
    for (int k0 = 0; k0 < kmax; k0 += 16) {
        float4 p = *(const float4*)(P + (size_t)(t0 + lr) * SEQ + k0 + lc);
        Ps[lc+0][lr] = p.x; Ps[lc+1][lr] = p.y; Ps[lc+2][lr] = p.z; Ps[lc+3][lr] = p.w;
        *(float4*)&Vs[vr][vc] = *(const float4*)(V + (size_t)(k0 + vr) * CH + n0 + vc);
        __syncthreads();
        #pragma unroll
        for (int kk = 0; kk < 16; kk++) {
            float4 af = *(const float4*)&Ps[kk][ty * 4];
            float4 bf = *(const float4*)&Vs[kk][tx * 4];
            const float afv[4] = {af.x, af.y, af.z, af.w};
            const float bfv[4] = {bf.x, bf.y, bf.z, bf.w};
            #pragma unroll
            for (int i = 0; i < 4; i++)
                #pragma unroll
                for (int j = 0; j < 4; j++)
                    acc[i][j] = fmaf(afv[i], bfv[j], acc[i][j]);
        }
        __syncthreads();
    }

    #pragma unroll
    for (int i = 0; i < 4; i++) {
        size_t off = ((size_t)b * SEQ + t0 + ty * 4 + i) * CH + n0 + tx * 4;
        *(float4*)(out + off) = make_float4(acc[i][0], acc[i][1], acc[i][2], acc[i][3]);
    }
}

// ---------------------------------------------------------------------------
extern "C" void kernel_launch(void* const* d_in, const int* in_sizes, int n_in,
                              void* d_out, int out_size)
{
    const float* x  = (const float*)d_in[0];
    const float* Wq = (const float*)d_in[1];
    const float* Wk = (const float*)d_in[2];
    const float* Wv = (const float*)d_in[3];
    float* out = (float*)d_out;

    qkv_kernel<<<dim3(CH / 64, MROWS / 64), 256>>>(x, Wq, Wk, Wv);
    scores_kernel<<<dim3(SEQ / 64, SEQ / 64, BATCH), 256>>>();
    softmax_kernel<<<dim3(SEQ, BATCH), 256>>>();
    av_kernel<<<dim3(CH / 64, SEQ / 64, BATCH), 256>>>(out);
}

// round 5
// speedup vs baseline: 2.4419x; 2.4419x over previous
#include <cuda_runtime.h>
#include <cuda_bf16.h>
#include <math_constants.h>
#include <cstdint>

#define BATCH 4
#define SEQ   2048
#define CH    1024
#define MROWS (BATCH * SEQ)   // 8192

// ---------------- scratch (device globals; allocation-free) ----------------
static __device__ __nv_bfloat16 g_xh[(size_t)MROWS * CH];
static __device__ __nv_bfloat16 g_xl[(size_t)MROWS * CH];
static __device__ __nv_bfloat16 g_wh[(size_t)3 * CH * CH];
static __device__ __nv_bfloat16 g_wl[(size_t)3 * CH * CH];
static __device__ __nv_bfloat16 g_qh[(size_t)MROWS * CH];
static __device__ __nv_bfloat16 g_ql[(size_t)MROWS * CH];
static __device__ __nv_bfloat16 g_kh[(size_t)MROWS * CH];
static __device__ __nv_bfloat16 g_kl[(size_t)MROWS * CH];
static __device__ __nv_bfloat16 g_vth[(size_t)BATCH * CH * SEQ];  // V^T: [b][c][s]
static __device__ __nv_bfloat16 g_vtl[(size_t)BATCH * CH * SEQ];
static __device__ float         g_S [(size_t)BATCH * SEQ * SEQ];
static __device__ __nv_bfloat16 g_ph[(size_t)BATCH * SEQ * SEQ];
static __device__ __nv_bfloat16 g_pl[(size_t)BATCH * SEQ * SEQ];

// ---------------- baseline-PTX helpers (no 'a'-target features) -----------
__device__ __forceinline__ uint32_t su32(const void* p) {
    uint32_t a;
    asm("{ .reg .u64 t; cvta.to.shared.u64 t, %1; cvt.u32.u64 %0, t; }"
        : "=r"(a) : "l"(p));
    return a;
}
__device__ __forceinline__ void cpasync16(uint32_t dst, const void* src) {
    asm volatile("cp.async.cg.shared.global [%0], [%1], 16;"
                 :: "r"(dst), "l"(src) : "memory");
}
__device__ __forceinline__ void cpcommit() {
    asm volatile("cp.async.commit_group;" ::: "memory");
}
template<int N> __device__ __forceinline__ void cpwait() {
    asm volatile("cp.async.wait_group %0;" :: "n"(N) : "memory");
}
__device__ __forceinline__ void ldsm4(uint32_t* r, uint32_t addr) {
    asm volatile("ldmatrix.sync.aligned.m8n8.x4.shared.b16 {%0,%1,%2,%3}, [%4];"
                 : "=r"(r[0]), "=r"(r[1]), "=r"(r[2]), "=r"(r[3]) : "r"(addr));
}
__device__ __forceinline__ void mma16816(float* d, const uint32_t* a,
                                         const uint32_t* b) {
    asm volatile(
        "mma.sync.aligned.m16n8k16.row.col.f32.bf16.bf16.f32 "
        "{%0,%1,%2,%3},{%4,%5,%6,%7},{%8,%9},{%0,%1,%2,%3};"
        : "+f"(d[0]), "+f"(d[1]), "+f"(d[2]), "+f"(d[3])
        : "r"(a[0]), "r"(a[1]), "r"(a[2]), "r"(a[3]), "r"(b[0]), "r"(b[1]));
}
__device__ __forceinline__ uint32_t pk(__nv_bfloat16 a, __nv_bfloat16 b) {
    uint16_t x = reinterpret_cast<uint16_t&>(a);
    uint16_t y = reinterpret_cast<uint16_t&>(b);
    return (uint32_t)x | ((uint32_t)y << 16);
}

// ---------------- smem tile geometry ----------------
// Tiles: 128 rows x 32 bf16 cols, padded row stride 40 bf16 = 80 bytes.
// Stage layout: Ah 0, Al 10240, Bh 20480, Bl 30720. Stage stride 40960.
#define T_STRIDE 80
#define OFF_AL   10240
#define OFF_BH   20480
#define OFF_BL   30720
#define STAGE_SZ 40960
#define SMEM_TOT (2 * STAGE_SZ)

// async-load one 128x32 bf16 tile (src at tile origin, ld in elements)
__device__ __forceinline__ void tile_ld(uint32_t sdst, const __nv_bfloat16* src,
                                        int ld, int tid) {
    #pragma unroll
    for (int it = 0; it < 2; it++) {
        int u = tid + it * 256;   // 0..511
        int r = u >> 2, q = u & 3;
        cpasync16(sdst + r * T_STRIDE + q * 16, src + (size_t)r * ld + q * 8);
    }
}

// compute one 128x128 x k32 chunk: acc += Ah*Bh + Ah*Bl + Al*Bh
__device__ __forceinline__ void compute_chunk(uint32_t sb, int wm0, int wn0,
                                              int lane, float acc[2][8][4]) {
    const int rowoff = lane & 15;
    const int koff   = (lane >> 4) * 16;   // bytes
    #pragma unroll
    for (int ks = 0; ks < 2; ks++) {
        const int kb = ks * 32 + koff;
        uint32_t ah[2][4], al[2][4], bb[8][2];
        #pragma unroll
        for (int mi = 0; mi < 2; mi++) {
            ldsm4(ah[mi], sb + (uint32_t)(wm0 + mi * 16 + rowoff) * T_STRIDE + kb);
            ldsm4(al[mi], sb + OFF_AL + (uint32_t)(wm0 + mi * 16 + rowoff) * T_STRIDE + kb);
        }
        #pragma unroll
        for (int nf = 0; nf < 4; nf++) {
            uint32_t r[4];
            ldsm4(r, sb + OFF_BH + (uint32_t)(wn0 + nf * 16 + rowoff) * T_STRIDE + kb);
            bb[nf*2][0] = r[0]; bb[nf*2+1][0] = r[1];
            bb[nf*2][1] = r[2]; bb[nf*2+1][1] = r[3];
        }
        #pragma unroll
        for (int mi = 0; mi < 2; mi++)
            #pragma unroll
            for (int ni = 0; ni < 8; ni++)
                mma16816(acc[mi][ni], ah[mi], bb[ni]);
        #pragma unroll
        for (int mi = 0; mi < 2; mi++)
            #pragma unroll
            for (int ni = 0; ni < 8; ni++)
                mma16816(acc[mi][ni], al[mi], bb[ni]);
        #pragma unroll
        for (int nf = 0; nf < 4; nf++) {
            uint32_t r[4];
            ldsm4(r, sb + OFF_BL + (uint32_t)(wn0 + nf * 16 + rowoff) * T_STRIDE + kb);
            bb[nf*2][0] = r[0]; bb[nf*2+1][0] = r[1];
            bb[nf*2][1] = r[2]; bb[nf*2+1][1] = r[3];
        }
        #pragma unroll
        for (int mi = 0; mi < 2; mi++)
            #pragma unroll
            for (int ni = 0; ni < 8; ni++)
                mma16816(acc[mi][ni], ah[mi], bb[ni]);
    }
}

// issue async loads for one k-chunk of all 4 tiles
__device__ __forceinline__ void chunk_ld(uint32_t sbase, int st,
                                         const __nv_bfloat16* Ah, const __nv_bfloat16* Al,
                                         const __nv_bfloat16* Bh, const __nv_bfloat16* Bl,
                                         int lda, int ldb, int k0, int tid) {
    const uint32_t s = sbase + st * STAGE_SZ;
    tile_ld(s,          Ah + k0, lda, tid);
    tile_ld(s + OFF_AL, Al + k0, lda, tid);
    tile_ld(s + OFF_BH, Bh + k0, ldb, tid);
    tile_ld(s + OFF_BL, Bl + k0, ldb, tid);
    cpcommit();
}

// main gemm loop: returns with acc filled
__device__ __forceinline__ void gemm_main(uint32_t sbase, int NK,
                                          const __nv_bfloat16* Ah, const __nv_bfloat16* Al,
                                          const __nv_bfloat16* Bh, const __nv_bfloat16* Bl,
                                          int lda, int ldb, int tid,
                                          int wm0, int wn0, float acc[2][8][4]) {
    const int lane = tid & 31;
    chunk_ld(sbase, 0, Ah, Al, Bh, Bl, lda, ldb, 0, tid);
    for (int kc = 0; kc < NK; kc++) {
        if (kc + 1 < NK) {
            chunk_ld(sbase, (kc + 1) & 1, Ah, Al, Bh, Bl, lda, ldb,
                     (kc + 1) * 32, tid);
            cpwait<1>();
        } else {
            cpwait<0>();
        }
        __syncthreads();
        compute_chunk(sbase + (kc & 1) * STAGE_SZ, wm0, wn0, lane, acc);
        __syncthreads();
    }
}

// ---------------------------------------------------------------------------
// Kernel 0: split fp32 input into bf16 hi/lo arrays
// ---------------------------------------------------------------------------
__global__ __launch_bounds__(256) void split_kernel(const float* __restrict__ src,
                                                    int which, int n) {
    __nv_bfloat16 *hi, *lo;
    switch (which) {
        case 0:  hi = g_xh;                    lo = g_xl;                    break;
        case 1:  hi = g_wh;                    lo = g_wl;                    break;
        case 2:  hi = g_wh + (size_t)CH*CH;    lo = g_wl + (size_t)CH*CH;    break;
        default: hi = g_wh + (size_t)2*CH*CH;  lo = g_wl + (size_t)2*CH*CH;  break;
    }
    int i = (blockIdx.x * 256 + threadIdx.x) * 4;
    if (i >= n) return;
    float4 v = *(const float4*)(src + i);
    __nv_bfloat16 h0 = __float2bfloat16(v.x), h1 = __float2bfloat16(v.y);
    __nv_bfloat16 h2 = __float2bfloat16(v.z), h3 = __float2bfloat16(v.w);
    *(uint32_t*)(hi + i)     = pk(h0, h1);
    *(uint32_t*)(hi + i + 2) = pk(h2, h3);
    *(uint32_t*)(lo + i)     = pk(__float2bfloat16(v.x - __bfloat162float(h0)),
                                  __float2bfloat16(v.y - __bfloat162float(h1)));
    *(uint32_t*)(lo + i + 2) = pk(__float2bfloat16(v.z - __bfloat162float(h2)),
                                  __float2bfloat16(v.w - __bfloat162float(h3)));
}

// ---------------------------------------------------------------------------
// Kernel 1: QKV projection. grid.x = (CH/128)*3 (matrix id = bx/8),
// grid.y = MROWS/128.
// ---------------------------------------------------------------------------
__global__ __launch_bounds__(256) void qkv_kernel() {
    extern __shared__ char sm[];
    const int tid = threadIdx.x, wid = tid >> 5, lane = tid & 31;
    const int mat = blockIdx.x >> 3;
    const int n0  = (blockIdx.x & 7) * 128;
    const int m0  = blockIdx.y * 128;
    const int wm0 = (wid & 3) * 32, wn0 = (wid >> 2) * 64;
    const uint32_t sbase = su32(sm);

    const __nv_bfloat16* Ah = g_xh + (size_t)m0 * CH;
    const __nv_bfloat16* Al = g_xl + (size_t)m0 * CH;
    const __nv_bfloat16* Bh = g_wh + (size_t)mat * CH * CH + (size_t)n0 * CH;
    const __nv_bfloat16* Bl = g_wl + (size_t)mat * CH * CH + (size_t)n0 * CH;

    float acc[2][8][4] = {};
    gemm_main(sbase, CH / 32, Ah, Al, Bh, Bl, CH, CH, tid, wm0, wn0, acc);

    const int qrow = lane >> 2, qcol = (lane & 3) * 2;
    if (mat < 2) {
        __nv_bfloat16* Hd = mat ? g_kh : g_qh;
        __nv_bfloat16* Ld = mat ? g_kl : g_ql;
        #pragma unroll
        for (int mi = 0; mi < 2; mi++)
            #pragma unroll
            for (int ni = 0; ni < 8; ni++)
                #pragma unroll
                for (int h = 0; h < 2; h++) {
                    float v0 = acc[mi][ni][h*2+0], v1 = acc[mi][ni][h*2+1];
                    int row = m0 + wm0 + mi*16 + qrow + h*8;
                    int col = n0 + wn0 + ni*8 + qcol;
                    __nv_bfloat16 h0 = __float2bfloat16(v0);
                    __nv_bfloat16 h1 = __float2bfloat16(v1);
                    *(uint32_t*)&Hd[(size_t)row * CH + col] = pk(h0, h1);
                    *(uint32_t*)&Ld[(size_t)row * CH + col] =
                        pk(__float2bfloat16(v0 - __bfloat162float(h0)),
                           __float2bfloat16(v1 - __bfloat162float(h1)));
                }
    } else {
        // V: transposed hi/lo store into [b][c][s]
        #pragma unroll
        for (int mi = 0; mi < 2; mi++)
            #pragma unroll
            for (int ni = 0; ni < 8; ni++)
                #pragma unroll
                for (int h = 0; h < 2; h++) {
                    int row = m0 + wm0 + mi*16 + qrow + h*8;   // token
                    int b = row >> 11, t = row & (SEQ - 1);
                    int col = n0 + wn0 + ni*8 + qcol;          // channel
                    #pragma unroll
                    for (int j = 0; j < 2; j++) {
                        float v = acc[mi][ni][h*2+j];
                        __nv_bfloat16 hh = __float2bfloat16(v);
                        size_t idx = ((size_t)b * CH + col + j) * SEQ + t;
                        g_vth[idx] = hh;
                        g_vtl[idx] = __float2bfloat16(v - __bfloat162float(hh));
                    }
                }
    }
}

// ---------------------------------------------------------------------------
// Kernel 2: scores S = (1/32) Q K^T, lower-triangular 128-tiles only.
// ---------------------------------------------------------------------------
__global__ __launch_bounds__(256) void scores_kernel() {
    if (blockIdx.x > blockIdx.y) return;
    extern __shared__ char sm[];
    const int tid = threadIdx.x, wid = tid >> 5, lane = tid & 31;
    const int b  = blockIdx.z;
    const int s0 = blockIdx.x * 128;
    const int t0 = blockIdx.y * 128;
    const int wm0 = (wid & 3) * 32, wn0 = (wid >> 2) * 64;
    const uint32_t sbase = su32(sm);

    const size_t ar = (size_t)(b * SEQ + t0) * CH;
    const size_t br = (size_t)(b * SEQ + s0) * CH;

    float acc[2][8][4] = {};
    gemm_main(sbase, CH / 32, g_qh + ar, g_ql + ar, g_kh + br, g_kl + br,
              CH, CH, tid, wm0, wn0, acc);

    const int qrow = lane >> 2, qcol = (lane & 3) * 2;
    const float sc = 0.03125f;
    #pragma unroll
    for (int mi = 0; mi < 2; mi++)
        #pragma unroll
        for (int ni = 0; ni < 8; ni++)
            #pragma unroll
            for (int h = 0; h < 2; h++) {
                int t = t0 + wm0 + mi*16 + qrow + h*8;
                int s = s0 + wn0 + ni*8 + qcol;
                *(float2*)&g_S[((size_t)b * SEQ + t) * SEQ + s] =
                    make_float2(acc[mi][ni][h*2] * sc, acc[mi][ni][h*2+1] * sc);
            }
}

// ---------------------------------------------------------------------------
// Kernel 3: row softmax (reads s<=t), writes P bf16 hi/lo, zeros to the
// 128-tile boundary.
// ---------------------------------------------------------------------------
__global__ __launch_bounds__(256) void softmax_kernel() {
    const int t = blockIdx.x;
    const int b = blockIdx.y;
    const size_t rowb = ((size_t)b * SEQ + t) * SEQ;
    const float* Srow = g_S + rowb;
    const int tid = threadIdx.x;
    const int len = ((t >> 7) + 1) << 7;

    float v[8];
    float m = -CUDART_INF_F;
    #pragma unroll
    for (int i = 0; i < 8; i++) {
        int s = tid + i * 256;
        v[i] = (s <= t) ? Srow[s] : -CUDART_INF_F;
        m = fmaxf(m, v[i]);
    }
    #pragma unroll
    for (int o = 16; o; o >>= 1) m = fmaxf(m, __shfl_xor_sync(~0u, m, o));
    __shared__ float smax[8], ssum[8];
    if ((tid & 31) == 0) smax[tid >> 5] = m;
    __syncthreads();
    m = smax[0];
    #pragma unroll
    for (int i = 1; i < 8; i++) m = fmaxf(m, smax[i]);

    float s = 0.f;
    #pragma unroll
    for (int i = 0; i < 8; i++) { v[i] = expf(v[i] - m); s += v[i]; }
    #pragma unroll
    for (int o = 16; o; o >>= 1) s += __shfl_xor_sync(~0u, s, o);
    if ((tid & 31) == 0) ssum[tid >> 5] = s;
    __syncthreads();
    s = 0.f;
    #pragma unroll
    for (int i = 0; i < 8; i++) s += ssum[i];
    const float inv = 1.0f / s;

    #pragma unroll
    for (int i = 0; i < 8; i++) {
        int sc = tid + i * 256;
        if (sc < len) {
            float p = v[i] * inv;
            __nv_bfloat16 h = __float2bfloat16(p);
            g_ph[rowb + sc] = h;
            g_pl[rowb + sc] = __float2bfloat16(p - __bfloat162float(h));
        }
    }
}

// ---------------------------------------------------------------------------
// Kernel 4: O = P V, B = V^T (K-major over s). k-loop clipped at t0+128.
// ---------------------------------------------------------------------------
__global__ __launch_bounds__(256) void pv_kernel(float* __restrict__ out) {
    extern __shared__ char sm[];
    const int tid = threadIdx.x, wid = tid >> 5, lane = tid & 31;
    const int b  = blockIdx.z;
    const int c0 = blockIdx.x * 128;
    const int t0 = blockIdx.y * 128;
    const int wm0 = (wid & 3) * 32, wn0 = (wid >> 2) * 64;
    const uint32_t sbase = su32(sm);

    const __nv_bfloat16* Ah = g_ph  + ((size_t)b * SEQ + t0) * SEQ;
    const __nv_bfloat16* Al = g_pl  + ((size_t)b * SEQ + t0) * SEQ;
    const __nv_bfloat16* Bh = g_vth + ((size_t)b * CH + c0) * SEQ;
    const __nv_bfloat16* Bl = g_vtl + ((size_t)b * CH + c0) * SEQ;

    float acc[2][8][4] = {};
    gemm_main(sbase, (t0 + 128) / 32, Ah, Al, Bh, Bl, SEQ, SEQ, tid,
              wm0, wn0, acc);

    const int qrow = lane >> 2, qcol = (lane & 3) * 2;
    #pragma unroll
    for (int mi = 0; mi < 2; mi++)
        #pragma unroll
        for (int ni = 0; ni < 8; ni++)
            #pragma unroll
            for (int h = 0; h < 2; h++) {
                int t = t0 + wm0 + mi*16 + qrow + h*8;
                int c = c0 + wn0 + ni*8 + qcol;
                *(float2*)&out[((size_t)b * SEQ + t) * CH + c] =
                    make_float2(acc[mi][ni][h*2], acc[mi][ni][h*2+1]);
            }
}

// ---------------------------------------------------------------------------
extern "C" void kernel_launch(void* const* d_in, const int* in_sizes, int n_in,
                              void* d_out, int out_size)
{
    const float* x  = (const float*)d_in[0];
    const float* Wq = (const float*)d_in[1];
    const float* Wk = (const float*)d_in[2];
    const float* Wv = (const float*)d_in[3];
    float* out = (float*)d_out;

    cudaFuncSetAttribute(qkv_kernel,
                         cudaFuncAttributeMaxDynamicSharedMemorySize, SMEM_TOT);
    cudaFuncSetAttribute(scores_kernel,
                         cudaFuncAttributeMaxDynamicSharedMemorySize, SMEM_TOT);
    cudaFuncSetAttribute(pv_kernel,
                         cudaFuncAttributeMaxDynamicSharedMemorySize, SMEM_TOT);

    split_kernel<<<MROWS * CH / 1024, 256>>>(x,  0, MROWS * CH);
    split_kernel<<<CH * CH / 1024,    256>>>(Wq, 1, CH * CH);
    split_kernel<<<CH * CH / 1024,    256>>>(Wk, 2, CH * CH);
    split_kernel<<<CH * CH / 1024,    256>>>(Wv, 3, CH * CH);

    qkv_kernel<<<dim3((CH / 128) * 3, MROWS / 128), 256, SMEM_TOT>>>();
    scores_kernel<<<dim3(SEQ / 128, SEQ / 128, BATCH), 256, SMEM_TOT>>>();
    softmax_kernel<<<dim3(SEQ, BATCH), 256>>>();
    pv_kernel<<<dim3(CH / 128, SEQ / 128, BATCH), 256, SMEM_TOT>>>(out);
}

// round 6
// speedup vs baseline: 2.4881x; 1.0189x over previous
#include <cuda_runtime.h>
#include <cuda_bf16.h>
#include <math_constants.h>
#include <cstdint>

#define BATCH 4
#define SEQ   2048
#define CH    1024
#define MROWS (BATCH * SEQ)   // 8192

// ---------------- scratch (device globals; allocation-free) ----------------
static __device__ __nv_bfloat16 g_xh[(size_t)MROWS * CH];
static __device__ __nv_bfloat16 g_xl[(size_t)MROWS * CH];
static __device__ __nv_bfloat16 g_wh[(size_t)3 * CH * CH];
static __device__ __nv_bfloat16 g_wl[(size_t)3 * CH * CH];
static __device__ __nv_bfloat16 g_qh[(size_t)MROWS * CH];
static __device__ __nv_bfloat16 g_ql[(size_t)MROWS * CH];
static __device__ __nv_bfloat16 g_kh[(size_t)MROWS * CH];
static __device__ __nv_bfloat16 g_kl[(size_t)MROWS * CH];
static __device__ __nv_bfloat16 g_vth[(size_t)BATCH * CH * SEQ];  // V^T: [b][c][s]
static __device__ __nv_bfloat16 g_vtl[(size_t)BATCH * CH * SEQ];
static __device__ float         g_S [(size_t)BATCH * SEQ * SEQ];
static __device__ __nv_bfloat16 g_ph[(size_t)BATCH * SEQ * SEQ];
static __device__ __nv_bfloat16 g_pl[(size_t)BATCH * SEQ * SEQ];

// ---------------- baseline-PTX helpers (no 'a'-target features) -----------
__device__ __forceinline__ uint32_t su32(const void* p) {
    uint32_t a;
    asm("{ .reg .u64 t; cvta.to.shared.u64 t, %1; cvt.u32.u64 %0, t; }"
        : "=r"(a) : "l"(p));
    return a;
}
__device__ __forceinline__ void cpasync16(uint32_t dst, const void* src) {
    asm volatile("cp.async.cg.shared.global [%0], [%1], 16;"
                 :: "r"(dst), "l"(src) : "memory");
}
__device__ __forceinline__ void cpcommit() {
    asm volatile("cp.async.commit_group;" ::: "memory");
}
template<int N> __device__ __forceinline__ void cpwait() {
    asm volatile("cp.async.wait_group %0;" :: "n"(N) : "memory");
}
__device__ __forceinline__ void ldsm4(uint32_t* r, uint32_t addr) {
    asm volatile("ldmatrix.sync.aligned.m8n8.x4.shared.b16 {%0,%1,%2,%3}, [%4];"
                 : "=r"(r[0]), "=r"(r[1]), "=r"(r[2]), "=r"(r[3]) : "r"(addr));
}
__device__ __forceinline__ void mma16816(float* d, const uint32_t* a,
                                         const uint32_t* b) {
    asm volatile(
        "mma.sync.aligned.m16n8k16.row.col.f32.bf16.bf16.f32 "
        "{%0,%1,%2,%3},{%4,%5,%6,%7},{%8,%9},{%0,%1,%2,%3};"
        : "+f"(d[0]), "+f"(d[1]), "+f"(d[2]), "+f"(d[3])
        : "r"(a[0]), "r"(a[1]), "r"(a[2]), "r"(a[3]), "r"(b[0]), "r"(b[1]));
}
__device__ __forceinline__ uint32_t pk(__nv_bfloat16 a, __nv_bfloat16 b) {
    uint16_t x = reinterpret_cast<uint16_t&>(a);
    uint16_t y = reinterpret_cast<uint16_t&>(b);
    return (uint32_t)x | ((uint32_t)y << 16);
}

// ---------------- smem tile geometry ----------------
// Tiles: 128 rows x 32 bf16 cols, padded row stride 40 bf16 = 80 bytes.
// Stage layout: Ah 0, Al 10240, Bh 20480, Bl 30720. Stage stride 40960.
#define T_STRIDE 80
#define OFF_AL   10240
#define OFF_BH   20480
#define OFF_BL   30720
#define STAGE_SZ 40960
#define SMEM_TOT (2 * STAGE_SZ)

// async-load one 128x32 bf16 tile (src at tile origin, ld in elements)
__device__ __forceinline__ void tile_ld(uint32_t sdst, const __nv_bfloat16* src,
                                        int ld, int tid) {
    #pragma unroll
    for (int it = 0; it < 2; it++) {
        int u = tid + it * 256;   // 0..511
        int r = u >> 2, q = u & 3;
        cpasync16(sdst + r * T_STRIDE + q * 16, src + (size_t)r * ld + q * 8);
    }
}

// compute one 128x128 x k32 chunk: acc += Ah*Bh + Ah*Bl + Al*Bh
__device__ __forceinline__ void compute_chunk(uint32_t sb, int wm0, int wn0,
                                              int lane, float acc[2][8][4]) {
    const int rowoff = lane & 15;
    const int koff   = (lane >> 4) * 16;   // bytes
    #pragma unroll
    for (int ks = 0; ks < 2; ks++) {
        const int kb = ks * 32 + koff;
        uint32_t ah[2][4], al[2][4], bb[8][2];
        #pragma unroll
        for (int mi = 0; mi < 2; mi++) {
            ldsm4(ah[mi], sb + (uint32_t)(wm0 + mi * 16 + rowoff) * T_STRIDE + kb);
            ldsm4(al[mi], sb + OFF_AL + (uint32_t)(wm0 + mi * 16 + rowoff) * T_STRIDE + kb);
        }
        #pragma unroll
        for (int nf = 0; nf < 4; nf++) {
            uint32_t r[4];
            ldsm4(r, sb + OFF_BH + (uint32_t)(wn0 + nf * 16 + rowoff) * T_STRIDE + kb);
            bb[nf*2][0] = r[0]; bb[nf*2+1][0] = r[1];
            bb[nf*2][1] = r[2]; bb[nf*2+1][1] = r[3];
        }
        #pragma unroll
        for (int mi = 0; mi < 2; mi++)
            #pragma unroll
            for (int ni = 0; ni < 8; ni++)
                mma16816(acc[mi][ni], ah[mi], bb[ni]);
        #pragma unroll
        for (int mi = 0; mi < 2; mi++)
            #pragma unroll
            for (int ni = 0; ni < 8; ni++)
                mma16816(acc[mi][ni], al[mi], bb[ni]);
        #pragma unroll
        for (int nf = 0; nf < 4; nf++) {
            uint32_t r[4];
            ldsm4(r, sb + OFF_BL + (uint32_t)(wn0 + nf * 16 + rowoff) * T_STRIDE + kb);
            bb[nf*2][0] = r[0]; bb[nf*2+1][0] = r[1];
            bb[nf*2][1] = r[2]; bb[nf*2+1][1] = r[3];
        }
        #pragma unroll
        for (int mi = 0; mi < 2; mi++)
            #pragma unroll
            for (int ni = 0; ni < 8; ni++)
                mma16816(acc[mi][ni], ah[mi], bb[ni]);
    }
}

// issue async loads for one k-chunk of all 4 tiles
__device__ __forceinline__ void chunk_ld(uint32_t sbase, int st,
                                         const __nv_bfloat16* Ah, const __nv_bfloat16* Al,
                                         const __nv_bfloat16* Bh, const __nv_bfloat16* Bl,
                                         int lda, int ldb, int k0, int tid) {
    const uint32_t s = sbase + st * STAGE_SZ;
    tile_ld(s,          Ah + k0, lda, tid);
    tile_ld(s + OFF_AL, Al + k0, lda, tid);
    tile_ld(s + OFF_BH, Bh + k0, ldb, tid);
    tile_ld(s + OFF_BL, Bl + k0, ldb, tid);
    cpcommit();
}

// main gemm loop: returns with acc filled
__device__ __forceinline__ void gemm_main(uint32_t sbase, int NK,
                                          const __nv_bfloat16* Ah, const __nv_bfloat16* Al,
                                          const __nv_bfloat16* Bh, const __nv_bfloat16* Bl,
                                          int lda, int ldb, int tid,
                                          int wm0, int wn0, float acc[2][8][4]) {
    const int lane = tid & 31;
    chunk_ld(sbase, 0, Ah, Al, Bh, Bl, lda, ldb, 0, tid);
    for (int kc = 0; kc < NK; kc++) {
        if (kc + 1 < NK) {
            chunk_ld(sbase, (kc + 1) & 1, Ah, Al, Bh, Bl, lda, ldb,
                     (kc + 1) * 32, tid);
            cpwait<1>();
        } else {
            cpwait<0>();
        }
        __syncthreads();
        compute_chunk(sbase + (kc & 1) * STAGE_SZ, wm0, wn0, lane, acc);
        __syncthreads();
    }
}

// ---------------------------------------------------------------------------
// Kernel 0: split fp32 inputs into bf16 hi/lo arrays (single launch).
// Region layout: [0, 8M) = x, [8M, 9M) = Wq, [9M, 10M) = Wk, [10M, 11M) = Wv.
// ---------------------------------------------------------------------------
__global__ __launch_bounds__(256) void split_kernel(
    const float* __restrict__ x,  const float* __restrict__ Wq,
    const float* __restrict__ Wk, const float* __restrict__ Wv) {
    const size_t NX = (size_t)MROWS * CH;   // 8M
    const size_t NW = (size_t)CH * CH;      // 1M
    size_t i = ((size_t)blockIdx.x * 256 + threadIdx.x) * 4;

    const float* src;
    __nv_bfloat16 *hi, *lo;
    size_t off;
    if (i < NX)               { src = x;  hi = g_xh; lo = g_xl; off = i; }
    else if (i < NX + NW)     { src = Wq; hi = g_wh; lo = g_wl; off = i - NX; }
    else if (i < NX + 2*NW)   { src = Wk; hi = g_wh + NW;   lo = g_wl + NW;   off = i - NX - NW; }
    else if (i < NX + 3*NW)   { src = Wv; hi = g_wh + 2*NW; lo = g_wl + 2*NW; off = i - NX - 2*NW; }
    else return;

    float4 v = *(const float4*)(src + off);
    __nv_bfloat16 h0 = __float2bfloat16(v.x), h1 = __float2bfloat16(v.y);
    __nv_bfloat16 h2 = __float2bfloat16(v.z), h3 = __float2bfloat16(v.w);
    *(uint32_t*)(hi + off)     = pk(h0, h1);
    *(uint32_t*)(hi + off + 2) = pk(h2, h3);
    *(uint32_t*)(lo + off)     = pk(__float2bfloat16(v.x - __bfloat162float(h0)),
                                    __float2bfloat16(v.y - __bfloat162float(h1)));
    *(uint32_t*)(lo + off + 2) = pk(__float2bfloat16(v.z - __bfloat162float(h2)),
                                    __float2bfloat16(v.w - __bfloat162float(h3)));
}

// ---------------------------------------------------------------------------
// Kernel 1: QKV projection. grid.x = (CH/128)*3 (matrix id = bx/8),
// grid.y = MROWS/128.
// ---------------------------------------------------------------------------
__global__ __launch_bounds__(256, 2) void qkv_kernel() {
    extern __shared__ char sm[];
    const int tid = threadIdx.x, wid = tid >> 5, lane = tid & 31;
    const int mat = blockIdx.x >> 3;
    const int n0  = (blockIdx.x & 7) * 128;
    const int m0  = blockIdx.y * 128;
    const int wm0 = (wid & 3) * 32, wn0 = (wid >> 2) * 64;
    const uint32_t sbase = su32(sm);

    const __nv_bfloat16* Ah = g_xh + (size_t)m0 * CH;
    const __nv_bfloat16* Al = g_xl + (size_t)m0 * CH;
    const __nv_bfloat16* Bh = g_wh + (size_t)mat * CH * CH + (size_t)n0 * CH;
    const __nv_bfloat16* Bl = g_wl + (size_t)mat * CH * CH + (size_t)n0 * CH;

    float acc[2][8][4] = {};
    gemm_main(sbase, CH / 32, Ah, Al, Bh, Bl, CH, CH, tid, wm0, wn0, acc);

    const int qrow = lane >> 2, qcol = (lane & 3) * 2;
    if (mat < 2) {
        __nv_bfloat16* Hd = mat ? g_kh : g_qh;
        __nv_bfloat16* Ld = mat ? g_kl : g_ql;
        #pragma unroll
        for (int mi = 0; mi < 2; mi++)
            #pragma unroll
            for (int ni = 0; ni < 8; ni++)
                #pragma unroll
                for (int h = 0; h < 2; h++) {
                    float v0 = acc[mi][ni][h*2+0], v1 = acc[mi][ni][h*2+1];
                    int row = m0 + wm0 + mi*16 + qrow + h*8;
                    int col = n0 + wn0 + ni*8 + qcol;
                    __nv_bfloat16 h0 = __float2bfloat16(v0);
                    __nv_bfloat16 h1 = __float2bfloat16(v1);
                    *(uint32_t*)&Hd[(size_t)row * CH + col] = pk(h0, h1);
                    *(uint32_t*)&Ld[(size_t)row * CH + col] =
                        pk(__float2bfloat16(v0 - __bfloat162float(h0)),
                           __float2bfloat16(v1 - __bfloat162float(h1)));
                }
    } else {
        // V: transposed hi/lo store into [b][c][s]
        #pragma unroll
        for (int mi = 0; mi < 2; mi++)
            #pragma unroll
            for (int ni = 0; ni < 8; ni++)
                #pragma unroll
                for (int h = 0; h < 2; h++) {
                    int row = m0 + wm0 + mi*16 + qrow + h*8;   // token
                    int b = row >> 11, t = row & (SEQ - 1);
                    int col = n0 + wn0 + ni*8 + qcol;          // channel
                    #pragma unroll
                    for (int j = 0; j < 2; j++) {
                        float v = acc[mi][ni][h*2+j];
                        __nv_bfloat16 hh = __float2bfloat16(v);
                        size_t idx = ((size_t)b * CH + col + j) * SEQ + t;
                        g_vth[idx] = hh;
                        g_vtl[idx] = __float2bfloat16(v - __bfloat162float(hh));
                    }
                }
    }
}

// ---------------------------------------------------------------------------
// Kernel 2: scores S = (1/32) Q K^T, lower-triangular 128-tiles only.
// ---------------------------------------------------------------------------
__global__ __launch_bounds__(256, 2) void scores_kernel() {
    if (blockIdx.x > blockIdx.y) return;
    extern __shared__ char sm[];
    const int tid = threadIdx.x, wid = tid >> 5, lane = tid & 31;
    const int b  = blockIdx.z;
    const int s0 = blockIdx.x * 128;
    const int t0 = blockIdx.y * 128;
    const int wm0 = (wid & 3) * 32, wn0 = (wid >> 2) * 64;
    const uint32_t sbase = su32(sm);

    const size_t ar = (size_t)(b * SEQ + t0) * CH;
    const size_t br = (size_t)(b * SEQ + s0) * CH;

    float acc[2][8][4] = {};
    gemm_main(sbase, CH / 32, g_qh + ar, g_ql + ar, g_kh + br, g_kl + br,
              CH, CH, tid, wm0, wn0, acc);

    const int qrow = lane >> 2, qcol = (lane & 3) * 2;
    const float sc = 0.03125f;
    #pragma unroll
    for (int mi = 0; mi < 2; mi++)
        #pragma unroll
        for (int ni = 0; ni < 8; ni++)
            #pragma unroll
            for (int h = 0; h < 2; h++) {
                int t = t0 + wm0 + mi*16 + qrow + h*8;
                int s = s0 + wn0 + ni*8 + qcol;
                *(float2*)&g_S[((size_t)b * SEQ + t) * SEQ + s] =
                    make_float2(acc[mi][ni][h*2] * sc, acc[mi][ni][h*2+1] * sc);
            }
}

// ---------------------------------------------------------------------------
// Kernel 3: row softmax (reads s<=t), writes P bf16 hi/lo, zeros to the
// 128-tile boundary.
// ---------------------------------------------------------------------------
__global__ __launch_bounds__(256) void softmax_kernel() {
    const int t = blockIdx.x;
    const int b = blockIdx.y;
    const size_t rowb = ((size_t)b * SEQ + t) * SEQ;
    const float* Srow = g_S + rowb;
    const int tid = threadIdx.x;
    const int len = ((t >> 7) + 1) << 7;

    float v[8];
    float m = -CUDART_INF_F;
    #pragma unroll
    for (int i = 0; i < 8; i++) {
        int s = tid + i * 256;
        v[i] = (s <= t) ? Srow[s] : -CUDART_INF_F;
        m = fmaxf(m, v[i]);
    }
    #pragma unroll
    for (int o = 16; o; o >>= 1) m = fmaxf(m, __shfl_xor_sync(~0u, m, o));
    __shared__ float smax[8], ssum[8];
    if ((tid & 31) == 0) smax[tid >> 5] = m;
    __syncthreads();
    m = smax[0];
    #pragma unroll
    for (int i = 1; i < 8; i++) m = fmaxf(m, smax[i]);

    float s = 0.f;
    #pragma unroll
    for (int i = 0; i < 8; i++) { v[i] = expf(v[i] - m); s += v[i]; }
    #pragma unroll
    for (int o = 16; o; o >>= 1) s += __shfl_xor_sync(~0u, s, o);
    if ((tid & 31) == 0) ssum[tid >> 5] = s;
    __syncthreads();
    s = 0.f;
    #pragma unroll
    for (int i = 0; i < 8; i++) s += ssum[i];
    const float inv = 1.0f / s;

    #pragma unroll
    for (int i = 0; i < 8; i++) {
        int sc = tid + i * 256;
        if (sc < len) {
            float p = v[i] * inv;
            __nv_bfloat16 h = __float2bfloat16(p);
            g_ph[rowb + sc] = h;
            g_pl[rowb + sc] = __float2bfloat16(p - __bfloat162float(h));
        }
    }
}

// ---------------------------------------------------------------------------
// Kernel 4: O = P V, B = V^T (K-major over s). k-loop clipped at t0+128.
// ---------------------------------------------------------------------------
__global__ __launch_bounds__(256, 2) void pv_kernel(float* __restrict__ out) {
    extern __shared__ char sm[];
    const int tid = threadIdx.x, wid = tid >> 5, lane = tid & 31;
    const int b  = blockIdx.z;
    const int c0 = blockIdx.x * 128;
    const int t0 = blockIdx.y * 128;
    const int wm0 = (wid & 3) * 32, wn0 = (wid >> 2) * 64;
    const uint32_t sbase = su32(sm);

    const __nv_bfloat16* Ah = g_ph  + ((size_t)b * SEQ + t0) * SEQ;
    const __nv_bfloat16* Al = g_pl  + ((size_t)b * SEQ + t0) * SEQ;
    const __nv_bfloat16* Bh = g_vth + ((size_t)b * CH + c0) * SEQ;
    const __nv_bfloat16* Bl = g_vtl + ((size_t)b * CH + c0) * SEQ;

    float acc[2][8][4] = {};
    gemm_main(sbase, (t0 + 128) / 32, Ah, Al, Bh, Bl, SEQ, SEQ, tid,
              wm0, wn0, acc);

    const int qrow = lane >> 2, qcol = (lane & 3) * 2;
    #pragma unroll
    for (int mi = 0; mi < 2; mi++)
        #pragma unroll
        for (int ni = 0; ni < 8; ni++)
            #pragma unroll
            for (int h = 0; h < 2; h++) {
                int t = t0 + wm0 + mi*16 + qrow + h*8;
                int c = c0 + wn0 + ni*8 + qcol;
                *(float2*)&out[((size_t)b * SEQ + t) * CH + c] =
                    make_float2(acc[mi][ni][h*2], acc[mi][ni][h*2+1]);
            }
}

// ---------------------------------------------------------------------------
extern "C" void kernel_launch(void* const* d_in, const int* in_sizes, int n_in,
                              void* d_out, int out_size)
{
    const float* x  = (const float*)d_in[0];
    const float* Wq = (const float*)d_in[1];
    const float* Wk = (const float*)d_in[2];
    const float* Wv = (const float*)d_in[3];
    float* out = (float*)d_out;

    cudaFuncSetAttribute(qkv_kernel,
                         cudaFuncAttributeMaxDynamicSharedMemorySize, SMEM_TOT);
    cudaFuncSetAttribute(scores_kernel,
                         cudaFuncAttributeMaxDynamicSharedMemorySize, SMEM_TOT);
    cudaFuncSetAttribute(pv_kernel,
                         cudaFuncAttributeMaxDynamicSharedMemorySize, SMEM_TOT);

    const size_t n_split = (size_t)MROWS * CH + 3 * (size_t)CH * CH;
    split_kernel<<<(unsigned)(n_split / 1024), 256>>>(x, Wq, Wk, Wv);

    qkv_kernel<<<dim3((CH / 128) * 3, MROWS / 128), 256, SMEM_TOT>>>();
    scores_kernel<<<dim3(SEQ / 128, SEQ / 128, BATCH), 256, SMEM_TOT>>>();
    softmax_kernel<<<dim3(SEQ, BATCH), 256>>>();
    pv_kernel<<<dim3(CH / 128, SEQ / 128, BATCH), 256, SMEM_TOT>>>(out);
}